// round 3
// baseline (speedup 1.0000x reference)
#include <cuda_runtime.h>
#include <cuda_bf16.h>
#include <cstdint>

#define USER_NUM 100000
#define ITEM_NUM 50000
#define N_NODES  (USER_NUM + ITEM_NUM)   // 150000
#define EMB      64
#define TOT      (N_NODES * EMB)         // 9,600,000 floats
#define USER_ELEMS (USER_NUM * EMB)      // 6,400,000

// Ping-pong scratch (static device memory; no runtime allocation)
__device__ float g_bufA[TOT];
__device__ float g_bufB[TOT];

// ---------------------------------------------------------------------------
// init: acc(d_out) = ego, h(bufA) = ego, next(bufB) = 0.  float4 vectorized.
// USER_ELEMS is divisible by 4, so no float4 chunk straddles the boundary.
// ---------------------------------------------------------------------------
__global__ void init_kernel(const float4* __restrict__ user4,
                            const float4* __restrict__ item4,
                            float4* __restrict__ out4,
                            float4* __restrict__ hA4,
                            float4* __restrict__ hB4) {
    int i = blockIdx.x * blockDim.x + threadIdx.x;
    if (i >= TOT / 4) return;
    float4 v;
    if (i < USER_ELEMS / 4) v = user4[i];
    else                    v = item4[i - USER_ELEMS / 4];
    out4[i] = v;
    hA4[i]  = v;
    hB4[i]  = make_float4(0.f, 0.f, 0.f, 0.f);
}

// ---------------------------------------------------------------------------
// SpMM (COO scatter): y[row[e]] += vals[e] * x[col[e]]   over EMB=64 dims
// One warp processes 32 edges: coalesced per-lane edge loads, then shuffle-
// broadcast. Per edge, each lane handles a float2 (coalesced 256B gather) and
// issues a single red.global.add.v2.f32 (no-return vector reduction).
// Edge stream uses __ldcs (evict-first) so x/y stay L2-resident.
// ---------------------------------------------------------------------------
__global__ void spmm_kernel(const int*   __restrict__ row,
                            const int*   __restrict__ col,
                            const float* __restrict__ vals,
                            const float* __restrict__ x,
                            float*       __restrict__ y,
                            int nnz) {
    int gwarp = (blockIdx.x * blockDim.x + threadIdx.x) >> 5;
    int lane  = threadIdx.x & 31;
    int base  = gwarp * 32;
    if (base >= nnz) return;

    int   r = 0, c = 0;
    float v = 0.f;
    int e = base + lane;
    if (e < nnz) {
        r = __ldcs(row  + e);
        c = __ldcs(col  + e);
        v = __ldcs(vals + e);
    }
    int cnt = nnz - base;
    if (cnt > 32) cnt = 32;

    #pragma unroll 4
    for (int j = 0; j < cnt; j++) {
        int   rr = __shfl_sync(0xffffffffu, r, j);
        int   cc = __shfl_sync(0xffffffffu, c, j);
        float vv = __shfl_sync(0xffffffffu, v, j);

        const float2* xp = reinterpret_cast<const float2*>(x + (size_t)cc * EMB) + lane;
        float2 xv = __ldg(xp);
        float a = vv * xv.x;
        float b = vv * xv.y;

        float* dst = y + (size_t)rr * EMB + lane * 2;
        asm volatile("red.global.add.v2.f32 [%0], {%1, %2};"
                     :: "l"(dst), "f"(a), "f"(b) : "memory");
    }
}

// ---------------------------------------------------------------------------
// acc += src ; zero the next layer's output buffer
// ---------------------------------------------------------------------------
__global__ void add_zero_kernel(float4* __restrict__ acc4,
                                const float4* __restrict__ src4,
                                float4* __restrict__ zero4) {
    int i = blockIdx.x * blockDim.x + threadIdx.x;
    if (i >= TOT / 4) return;
    float4 a = acc4[i];
    float4 s = src4[i];
    a.x += s.x; a.y += s.y; a.z += s.z; a.w += s.w;
    acc4[i] = a;
    zero4[i] = make_float4(0.f, 0.f, 0.f, 0.f);
}

// ---------------------------------------------------------------------------
// acc = (acc + src) * 0.25  (final layer: fold in mean over 4 terms)
// ---------------------------------------------------------------------------
__global__ void add_scale_kernel(float4* __restrict__ acc4,
                                 const float4* __restrict__ src4) {
    int i = blockIdx.x * blockDim.x + threadIdx.x;
    if (i >= TOT / 4) return;
    float4 a = acc4[i];
    float4 s = src4[i];
    a.x = (a.x + s.x) * 0.25f;
    a.y = (a.y + s.y) * 0.25f;
    a.z = (a.z + s.z) * 0.25f;
    a.w = (a.w + s.w) * 0.25f;
    acc4[i] = a;
}

extern "C" void kernel_launch(void* const* d_in, const int* in_sizes, int n_in,
                              void* d_out, int out_size) {
    const float* user_emb = (const float*)d_in[0];
    const float* item_emb = (const float*)d_in[1];
    const int*   adj_row  = (const int*)  d_in[2];
    const int*   adj_col  = (const int*)  d_in[3];
    const float* adj_vals = (const float*)d_in[4];
    float* out = (float*)d_out;
    int nnz = in_sizes[2];

    float* bufA; cudaGetSymbolAddress((void**)&bufA, g_bufA);
    float* bufB; cudaGetSymbolAddress((void**)&bufB, g_bufB);

    const int EW_THREADS = 256;
    const int EW_BLOCKS  = (TOT / 4 + EW_THREADS - 1) / EW_THREADS;

    const int SP_THREADS = 256;                       // 8 warps / block
    int nwarps = (nnz + 31) / 32;
    int SP_BLOCKS = (nwarps + (SP_THREADS / 32) - 1) / (SP_THREADS / 32);

    // acc = ego ; h = ego (bufA) ; bufB = 0
    init_kernel<<<EW_BLOCKS, EW_THREADS>>>(
        (const float4*)user_emb, (const float4*)item_emb,
        (float4*)out, (float4*)bufA, (float4*)bufB);

    // layer 1: h1 = A*h0   (A reads bufA, writes bufB)
    spmm_kernel<<<SP_BLOCKS, SP_THREADS>>>(adj_row, adj_col, adj_vals, bufA, bufB, nnz);
    // acc += h1 ; zero bufA for next layer output
    add_zero_kernel<<<EW_BLOCKS, EW_THREADS>>>((float4*)out, (const float4*)bufB, (float4*)bufA);

    // layer 2: h2 = A*h1   (reads bufB, writes bufA)
    spmm_kernel<<<SP_BLOCKS, SP_THREADS>>>(adj_row, adj_col, adj_vals, bufB, bufA, nnz);
    // acc += h2 ; zero bufB for next layer output
    add_zero_kernel<<<EW_BLOCKS, EW_THREADS>>>((float4*)out, (const float4*)bufA, (float4*)bufB);

    // layer 3: h3 = A*h2   (reads bufA, writes bufB)
    spmm_kernel<<<SP_BLOCKS, SP_THREADS>>>(adj_row, adj_col, adj_vals, bufA, bufB, nnz);
    // acc = (acc + h3) / 4
    add_scale_kernel<<<EW_BLOCKS, EW_THREADS>>>((float4*)out, (const float4*)bufB);
}

// round 4
// speedup vs baseline: 1.3650x; 1.3650x over previous
#include <cuda_runtime.h>
#include <cuda_bf16.h>
#include <cstdint>

#define USER_NUM 100000
#define ITEM_NUM 50000
#define N_NODES  (USER_NUM + ITEM_NUM)   // 150000
#define EMB      64
#define TOT      (N_NODES * EMB)         // 9,600,000 floats
#define USER_ELEMS (USER_NUM * EMB)      // 6,400,000
#define NNZ_MAX  4800000
#define SCAN_CHUNK 1024
#define NCHUNK   ((N_NODES + SCAN_CHUNK - 1) / SCAN_CHUNK)   // 147

// Static device scratch (no runtime allocation allowed)
__device__ float g_bufA[TOT];
__device__ float g_bufB[TOT];
__device__ int   g_rowptr[N_NODES + 1];
__device__ int   g_cursor[N_NODES];
__device__ int   g_counts[N_NODES];
__device__ int2  g_edges[NNZ_MAX];       // packed (col, val-bits), row-sorted
__device__ int   g_partial[256];
__device__ int   g_pex[256];

// ---------------------------------------------------------------------------
// init: acc(d_out) = ego, h0(bufA) = ego ; zero row histogram.
// ---------------------------------------------------------------------------
__global__ void init_kernel(const float4* __restrict__ user4,
                            const float4* __restrict__ item4,
                            float4* __restrict__ out4,
                            float4* __restrict__ hA4,
                            int* __restrict__ counts) {
    int i = blockIdx.x * blockDim.x + threadIdx.x;
    if (i < TOT / 4) {
        float4 v = (i < USER_ELEMS / 4) ? user4[i] : item4[i - USER_ELEMS / 4];
        out4[i] = v;
        hA4[i]  = v;
    }
    if (i < N_NODES) counts[i] = 0;
}

// ---------------------------------------------------------------------------
// Counting-sort stage 1: per-row histogram
// ---------------------------------------------------------------------------
__global__ void hist_kernel(const int* __restrict__ row,
                            int* __restrict__ counts, int nnz) {
    int i = blockIdx.x * blockDim.x + threadIdx.x;
    if (i < nnz) atomicAdd(&counts[__ldcs(row + i)], 1);
}

// ---------------------------------------------------------------------------
// Counting-sort stage 2: 3-kernel exclusive scan of counts -> rowptr, cursor
// ---------------------------------------------------------------------------
__global__ void scan_reduce(const int* __restrict__ counts,
                            int* __restrict__ partial) {
    __shared__ int s[SCAN_CHUNK];
    int i = blockIdx.x * SCAN_CHUNK + threadIdx.x;
    s[threadIdx.x] = (i < N_NODES) ? counts[i] : 0;
    __syncthreads();
    for (int st = SCAN_CHUNK / 2; st > 0; st >>= 1) {
        if (threadIdx.x < st) s[threadIdx.x] += s[threadIdx.x + st];
        __syncthreads();
    }
    if (threadIdx.x == 0) partial[blockIdx.x] = s[0];
}

__global__ void scan_partials(const int* __restrict__ partial,
                              int* __restrict__ pex, int n) {
    __shared__ int s[256];
    int v = (threadIdx.x < n) ? partial[threadIdx.x] : 0;
    s[threadIdx.x] = v;
    __syncthreads();
    for (int st = 1; st < 256; st <<= 1) {
        int t = (threadIdx.x >= st) ? s[threadIdx.x - st] : 0;
        __syncthreads();
        s[threadIdx.x] += t;
        __syncthreads();
    }
    if (threadIdx.x < n) pex[threadIdx.x] = s[threadIdx.x] - v;   // exclusive
}

__global__ void scan_final(const int* __restrict__ counts,
                           const int* __restrict__ pex,
                           int* __restrict__ rowptr,
                           int* __restrict__ cursor, int nnz) {
    __shared__ int s[SCAN_CHUNK];
    int i = blockIdx.x * SCAN_CHUNK + threadIdx.x;
    int v = (i < N_NODES) ? counts[i] : 0;
    s[threadIdx.x] = v;
    __syncthreads();
    for (int st = 1; st < SCAN_CHUNK; st <<= 1) {
        int t = (threadIdx.x >= st) ? s[threadIdx.x - st] : 0;
        __syncthreads();
        s[threadIdx.x] += t;
        __syncthreads();
    }
    if (i < N_NODES) {
        int ex = pex[blockIdx.x] + s[threadIdx.x] - v;   // exclusive prefix
        rowptr[i] = ex;
        cursor[i] = ex;
    }
    if (i == 0) rowptr[N_NODES] = nnz;
}

// ---------------------------------------------------------------------------
// Counting-sort stage 3: scatter edges into row-sorted packed array
// ---------------------------------------------------------------------------
__global__ void scatter_kernel(const int* __restrict__ row,
                               const int* __restrict__ col,
                               const float* __restrict__ vals,
                               int* __restrict__ cursor,
                               int2* __restrict__ edges, int nnz) {
    int i = blockIdx.x * blockDim.x + threadIdx.x;
    if (i < nnz) {
        int r = __ldcs(row + i);
        int p = atomicAdd(&cursor[r], 1);
        edges[p] = make_int2(__ldcs(col + i), __float_as_int(__ldcs(vals + i)));
    }
}

// ---------------------------------------------------------------------------
// CSR SpMM, warp per row, segmented register accumulation, NO atomics.
// Each lane owns a float2 of the 64-wide embedding. Edge metadata is a
// warp-uniform 8B load (1 sector; 16 edges/line so mostly L1 hits).
// Epilogue fuses acc += h (and the final /4 scale) — no separate passes.
// ---------------------------------------------------------------------------
template<bool FINAL>
__global__ void spmm_csr(const int* __restrict__ rowptr,
                         const int2* __restrict__ edges,
                         const float* __restrict__ x,
                         float* __restrict__ y,
                         float* __restrict__ acc) {
    int warp = (blockIdx.x * blockDim.x + threadIdx.x) >> 5;
    int lane = threadIdx.x & 31;
    if (warp >= N_NODES) return;

    int start = __ldg(rowptr + warp);
    int end   = __ldg(rowptr + warp + 1);

    float ax = 0.f, ay = 0.f;
    int e = start;
    // 4-wide manual unroll for memory-level parallelism
    for (; e + 4 <= end; e += 4) {
        int2 e0 = __ldg(edges + e + 0);
        int2 e1 = __ldg(edges + e + 1);
        int2 e2 = __ldg(edges + e + 2);
        int2 e3 = __ldg(edges + e + 3);
        float2 x0 = __ldg(reinterpret_cast<const float2*>(x + (size_t)e0.x * EMB) + lane);
        float2 x1 = __ldg(reinterpret_cast<const float2*>(x + (size_t)e1.x * EMB) + lane);
        float2 x2 = __ldg(reinterpret_cast<const float2*>(x + (size_t)e2.x * EMB) + lane);
        float2 x3 = __ldg(reinterpret_cast<const float2*>(x + (size_t)e3.x * EMB) + lane);
        ax = fmaf(__int_as_float(e0.y), x0.x, ax);
        ay = fmaf(__int_as_float(e0.y), x0.y, ay);
        ax = fmaf(__int_as_float(e1.y), x1.x, ax);
        ay = fmaf(__int_as_float(e1.y), x1.y, ay);
        ax = fmaf(__int_as_float(e2.y), x2.x, ax);
        ay = fmaf(__int_as_float(e2.y), x2.y, ay);
        ax = fmaf(__int_as_float(e3.y), x3.x, ax);
        ay = fmaf(__int_as_float(e3.y), x3.y, ay);
    }
    for (; e < end; ++e) {
        int2 ed = __ldg(edges + e);
        float2 xv = __ldg(reinterpret_cast<const float2*>(x + (size_t)ed.x * EMB) + lane);
        float v = __int_as_float(ed.y);
        ax = fmaf(v, xv.x, ax);
        ay = fmaf(v, xv.y, ay);
    }

    float2* ap = reinterpret_cast<float2*>(acc + (size_t)warp * EMB) + lane;
    float2 a = *ap;
    if (FINAL) {
        a.x = (a.x + ax) * 0.25f;
        a.y = (a.y + ay) * 0.25f;
        *ap = a;
    } else {
        float2* yp = reinterpret_cast<float2*>(y + (size_t)warp * EMB) + lane;
        *yp = make_float2(ax, ay);
        a.x += ax;
        a.y += ay;
        *ap = a;
    }
}

extern "C" void kernel_launch(void* const* d_in, const int* in_sizes, int n_in,
                              void* d_out, int out_size) {
    const float* user_emb = (const float*)d_in[0];
    const float* item_emb = (const float*)d_in[1];
    const int*   adj_row  = (const int*)  d_in[2];
    const int*   adj_col  = (const int*)  d_in[3];
    const float* adj_vals = (const float*)d_in[4];
    float* out = (float*)d_out;
    int nnz = in_sizes[2];

    float* bufA;   cudaGetSymbolAddress((void**)&bufA,   g_bufA);
    float* bufB;   cudaGetSymbolAddress((void**)&bufB,   g_bufB);
    int*   rowptr; cudaGetSymbolAddress((void**)&rowptr, g_rowptr);
    int*   cursor; cudaGetSymbolAddress((void**)&cursor, g_cursor);
    int*   counts; cudaGetSymbolAddress((void**)&counts, g_counts);
    int2*  edges;  cudaGetSymbolAddress((void**)&edges,  g_edges);
    int*   partial;cudaGetSymbolAddress((void**)&partial,g_partial);
    int*   pex;    cudaGetSymbolAddress((void**)&pex,    g_pex);

    const int T = 256;
    const int EW_BLOCKS = (TOT / 4 + T - 1) / T;         // covers N_NODES too
    const int EG_BLOCKS = (nnz + T - 1) / T;
    const int SP_BLOCKS = (N_NODES * 32 + T - 1) / T;    // warp per row

    // acc = ego ; h0 = ego ; counts = 0
    init_kernel<<<EW_BLOCKS, T>>>((const float4*)user_emb, (const float4*)item_emb,
                                  (float4*)out, (float4*)bufA, counts);

    // counting sort by row -> CSR (rowptr + packed (col,val) edges)
    hist_kernel<<<EG_BLOCKS, T>>>(adj_row, counts, nnz);
    scan_reduce<<<NCHUNK, SCAN_CHUNK>>>(counts, partial);
    scan_partials<<<1, 256>>>(partial, pex, NCHUNK);
    scan_final<<<NCHUNK, SCAN_CHUNK>>>(counts, pex, rowptr, cursor, nnz);
    scatter_kernel<<<EG_BLOCKS, T>>>(adj_row, adj_col, adj_vals, cursor, edges, nnz);

    // layer 1: h1 = A*h0 (bufA->bufB), acc += h1
    spmm_csr<false><<<SP_BLOCKS, T>>>(rowptr, edges, bufA, bufB, out);
    // layer 2: h2 = A*h1 (bufB->bufA), acc += h2
    spmm_csr<false><<<SP_BLOCKS, T>>>(rowptr, edges, bufB, bufA, out);
    // layer 3: h3 = A*h2 (bufA->unused), acc = (acc + h3)/4
    spmm_csr<true><<<SP_BLOCKS, T>>>(rowptr, edges, bufA, bufB, out);
}